// round 3
// baseline (speedup 1.0000x reference)
#include <cuda_runtime.h>
#include <cstdint>
#include <math.h>

#define EPS   1e-5f
#define BB    2
#define NN    512
#define DD    64

typedef unsigned long long ull;

// ---------------- device scratch (no allocations allowed) ----------------
__device__ __align__(16) float g_U   [BB*NN*128];   // s1 * (W1a @ f_i), [node][128]
__device__ __align__(16) float g_Vt  [BB*128*NN];   // k-major: [b][k][j]
__device__ __align__(16) float g_nfn [BB*NN*DD];    // normalized node features
__device__ __align__(16) float g_W2t [128*64];      // k-major BN-folded [k][o]
__device__ __align__(16) ull   g_W3p [64*32];       // k-major BN-folded, dup-packed [kk][o]
__device__ float g_c2[64];
__device__ float g_c3[32];
__device__ float g_w4[32];
__device__ float g_b4s;
__device__ __align__(16) float g_L   [BB*NN*NN];    // raw MLP logits
__device__ int   g_active[BB];

// ---------------- fp32x2 packed helpers (sm_103a) ----------------
__device__ __forceinline__ void fma2(ull &d, ull a, ull b) {
    asm("fma.rn.f32x2 %0, %1, %2, %0;" : "+l"(d) : "l"(a), "l"(b));
}
__device__ __forceinline__ ull add2(ull a, ull b) {
    ull d; asm("add.rn.f32x2 %0, %1, %2;" : "=l"(d) : "l"(a), "l"(b)); return d;
}
__device__ __forceinline__ void unpack2(ull v, float &lo, float &hi) {
    unsigned a, b;
    asm("mov.b64 {%0, %1}, %2;" : "=r"(a), "=r"(b) : "l"(v));
    lo = __uint_as_float(a); hi = __uint_as_float(b);
}

// ---------------- smem layout for k_main (dynamic) ----------------
#define OFF_W2   0                       // ull[128][32]  = 32768
#define OFF_W3   32768                   // ull[64][32]   = 16384
#define OFF_AH   49152                   // ACT ull[16][128]=16384  UNION  H2T f32[64][128]=32768
#define OFF_US   81920                   // f32[128][8]   = 4096
#define OFF_VS   86016                   // f32[128][16]  = 8192
#define OFF_H3   94208                   // f32[128][9]   = 4608
#define OFF_C2   98816                   // ull[32]       = 256
#define OFF_C3   99072                   // f32[32]
#define OFF_W4   99200                   // f32[32]
#define OFF_B4   99328                   // f32[1]
#define SMEM_TOTAL 99344

// ---------------- prep: fold BN into W2/W3, consts, active flags ----------
__global__ void k_fold(const float* __restrict__ W2, const float* __restrict__ b2,
                       const float* __restrict__ g2, const float* __restrict__ be2,
                       const float* __restrict__ m2, const float* __restrict__ v2,
                       const float* __restrict__ W3, const float* __restrict__ b3,
                       const float* __restrict__ g3, const float* __restrict__ be3,
                       const float* __restrict__ m3, const float* __restrict__ v3,
                       const float* __restrict__ W4, const float* __restrict__ b4,
                       const int* __restrict__ masks) {
    int t = threadIdx.x;
    for (int idx = t; idx < 64 * 128; idx += blockDim.x) {
        int o = idx / 128, k = idx % 128;
        float s = g2[o] * rsqrtf(v2[o] + EPS);
        g_W2t[k * 64 + o] = W2[o * 128 + k] * s;
    }
    for (int idx = t; idx < 64 * 32; idx += blockDim.x) {
        int kk = idx / 32, o = idx % 32;
        float s = g3[o] * rsqrtf(v3[o] + EPS);
        float w = W3[o * 64 + kk] * s;
        unsigned u = __float_as_uint(w);
        g_W3p[idx] = ((ull)u << 32) | (ull)u;
    }
    if (t < 64) {
        float s = g2[t] * rsqrtf(v2[t] + EPS);
        g_c2[t] = (b2[t] - m2[t]) * s + be2[t];
    }
    if (t < 32) {
        float s = g3[t] * rsqrtf(v3[t] + EPS);
        g_c3[t] = (b3[t] - m3[t]) * s + be3[t];
        g_w4[t] = W4[t];
    }
    if (t == 0) g_b4s = b4[0];
    // active flags
    __shared__ int cnt[BB];
    if (t < BB) cnt[t] = 0;
    __syncthreads();
    for (int idx = t; idx < BB * NN; idx += blockDim.x)
        if (masks[idx] != 0) atomicAdd(&cnt[idx / NN], 1);
    __syncthreads();
    if (t < BB) g_active[t] = (cnt[t] > 1) ? 1 : 0;
}

// ---------------- prep: per-node U, Vt, normalized features ----------------
__global__ void k_nodes(const float* __restrict__ f,
                        const float* __restrict__ W1, const float* __restrict__ b1,
                        const float* __restrict__ g1, const float* __restrict__ be1,
                        const float* __restrict__ m1, const float* __restrict__ v1) {
    __shared__ float fs[DD];
    __shared__ float sinv;
    int node = blockIdx.x;
    int b = node / NN, i = node % NN;
    int t = threadIdx.x;                 // 0..127 = output channel o
    if (t < DD) fs[t] = f[node * DD + t];
    __syncthreads();
    if (t == 0) {
        float ss = 0.f;
        for (int d = 0; d < DD; d++) ss += fs[d] * fs[d];
        sinv = 1.f / fmaxf(sqrtf(ss), 1e-12f);
    }
    __syncthreads();
    if (t < DD) g_nfn[node * DD + t] = fs[t] * sinv;

    float s1 = g1[t] * rsqrtf(v1[t] + EPS);
    float u = 0.f, vv = 0.f;
    const float* wr = &W1[t * 128];
    #pragma unroll 8
    for (int d = 0; d < DD; d++) {
        u  += wr[d]      * fs[d];
        vv += wr[DD + d] * fs[d];
    }
    g_U[node * 128 + t] = u * s1;
    g_Vt[(b * 128 + t) * NN + i] = vv * s1 + (b1[t] - m1[t]) * s1 + be1[t];
}

// ---------------- main: register-tiled fused MLP ----------------
// Block: 256 threads, tile = 8 i x 16 j = 128 pairs, all 64 L2-outs.
// Thread micro-tile: 4 pairs (pg = t&31 -> pairs 4pg..4pg+3, same set of 4 jj, ii=pg/4... )
//   pairs p = ii*16+jj linearized; thread owns p in [4pg, 4pg+4)
//   out group og = t>>5: layer2 outs [8og,8og+8), layer3 outs [4og,4og+4)
__global__ __launch_bounds__(256, 2)
void k_main() {
    extern __shared__ char sm[];
    ull*   W2s = (ull*)  (sm + OFF_W2);   // [k][32] outs (2q,2q+1)
    ull*   W3s = (ull*)  (sm + OFF_W3);   // [kk][32] dup-packed
    ull*   ACT = (ull*)  (sm + OFF_AH);   // [16][128] dup-packed act
    float* H2T = (float*)(sm + OFF_AH);   // [64][128] relu(h2+c2), aliases ACT
    float* Us  = (float*)(sm + OFF_US);   // [k][8]
    float* Vs  = (float*)(sm + OFF_VS);   // [k][16]
    float* H3s = (float*)(sm + OFF_H3);   // [128][9]
    ull*   c2p = (ull*)  (sm + OFF_C2);   // [32] (c2[2q],c2[2q+1])
    float* c3s = (float*)(sm + OFF_C3);
    float* w4s = (float*)(sm + OFF_W4);
    float* b4s = (float*)(sm + OFF_B4);

    int b  = blockIdx.z;
    int i0 = blockIdx.y * 8;
    int j0 = blockIdx.x * 16;
    int t  = threadIdx.x;

    {
        const ull* w2g = (const ull*)g_W2t;
        #pragma unroll 4
        for (int idx = t; idx < 128 * 32; idx += 256) W2s[idx] = w2g[idx];
        #pragma unroll 2
        for (int idx = t; idx < 64 * 32; idx += 256)  W3s[idx] = g_W3p[idx];
        #pragma unroll 2
        for (int idx = t; idx < 8 * 128; idx += 256) {
            int ii = idx >> 7, k = idx & 127;
            Us[k * 8 + ii] = g_U[(b * NN + i0 + ii) * 128 + k];
        }
        #pragma unroll 4
        for (int idx = t; idx < 16 * 128; idx += 256) {
            int k = idx >> 4, jj = idx & 15;
            Vs[k * 16 + jj] = g_Vt[(b * 128 + k) * NN + j0 + jj];
        }
        if (t < 32) {
            unsigned lo = __float_as_uint(g_c2[2 * t]);
            unsigned hi = __float_as_uint(g_c2[2 * t + 1]);
            c2p[t] = ((ull)hi << 32) | (ull)lo;
        } else if (t < 64) c3s[t - 32] = g_c3[t - 32];
        else if (t < 96)   w4s[t - 64] = g_w4[t - 64];
        else if (t == 96)  b4s[0] = g_b4s;
    }
    __syncthreads();

    int pg = t & 31;
    int og = t >> 5;

    ull A[4][4];
    #pragma unroll
    for (int s = 0; s < 4; s++)
        #pragma unroll
        for (int w = 0; w < 4; w++) A[s][w] = 0ull;

    // ---- Layer 2 over 8 chunks of 16 k ----
    for (int c = 0; c < 8; c++) {
        // stage packed-dup activations: ACT[kl][p] = dup(relu(U[i(p)][k]+V[j(p)][k]))
        #pragma unroll
        for (int it = 0; it < 8; it++) {
            int idx = t + it * 256;
            int p = idx & 127, kl = idx >> 7;
            int k = c * 16 + kl;
            float a = fmaxf(Us[k * 8 + (p >> 4)] + Vs[k * 16 + (p & 15)], 0.f);
            ((float2*)ACT)[kl * 128 + p] = make_float2(a, a);
        }
        __syncthreads();
        #pragma unroll
        for (int kl = 0; kl < 16; kl++) {
            ulonglong2 a01 = *(const ulonglong2*)&ACT[kl * 128 + 4 * pg];
            ulonglong2 a23 = *(const ulonglong2*)&ACT[kl * 128 + 4 * pg + 2];
            int k = c * 16 + kl;
            ulonglong2 w01 = *(const ulonglong2*)&W2s[k * 32 + 4 * og];
            ulonglong2 w23 = *(const ulonglong2*)&W2s[k * 32 + 4 * og + 2];
            ull av[4] = { a01.x, a01.y, a23.x, a23.y };
            ull wv[4] = { w01.x, w01.y, w23.x, w23.y };
            #pragma unroll
            for (int s = 0; s < 4; s++)
                #pragma unroll
                for (int w = 0; w < 4; w++) fma2(A[s][w], av[s], wv[w]);
        }
        __syncthreads();
    }

    // ---- add c2, relu, write H2T[o][p] (transposed exchange) ----
    #pragma unroll
    for (int w = 0; w < 4; w++) {
        ull cp = c2p[4 * og + w];
        float vlo[4], vhi[4];
        #pragma unroll
        for (int s = 0; s < 4; s++) {
            float lo, hi;
            unpack2(add2(A[s][w], cp), lo, hi);
            vlo[s] = fmaxf(lo, 0.f);
            vhi[s] = fmaxf(hi, 0.f);
        }
        int o0 = 8 * og + 2 * w;
        *(float4*)&H2T[o0 * 128 + 4 * pg]       = make_float4(vlo[0], vlo[1], vlo[2], vlo[3]);
        *(float4*)&H2T[(o0 + 1) * 128 + 4 * pg] = make_float4(vhi[0], vhi[1], vhi[2], vhi[3]);
    }
    __syncthreads();

    // ---- Layer 3: f32x2 over pair-dim; B[pu][o] = pairs (4pg+2pu, +1), out 4og+o ----
    ull B[2][4];
    #pragma unroll
    for (int pu = 0; pu < 2; pu++)
        #pragma unroll
        for (int o = 0; o < 4; o++) B[pu][o] = 0ull;

    #pragma unroll 8
    for (int kk = 0; kk < 64; kk++) {
        ulonglong2 av  = *(const ulonglong2*)&H2T[kk * 128 + 4 * pg];
        ulonglong2 w01 = *(const ulonglong2*)&W3s[kk * 32 + 4 * og];
        ulonglong2 w23 = *(const ulonglong2*)&W3s[kk * 32 + 4 * og + 2];
        ull wv[4] = { w01.x, w01.y, w23.x, w23.y };
        #pragma unroll
        for (int o = 0; o < 4; o++) {
            fma2(B[0][o], av.x, wv[o]);
            fma2(B[1][o], av.y, wv[o]);
        }
    }

    // ---- head partials: per pair sum over this thread's 4 outs ----
    {
        float p0 = 0.f, p1 = 0.f, p2 = 0.f, p3 = 0.f;
        #pragma unroll
        for (int o = 0; o < 4; o++) {
            float c3v = c3s[4 * og + o], w4v = w4s[4 * og + o];
            float lo, hi;
            unpack2(B[0][o], lo, hi);
            p0 += fmaxf(lo + c3v, 0.f) * w4v;
            p1 += fmaxf(hi + c3v, 0.f) * w4v;
            unpack2(B[1][o], lo, hi);
            p2 += fmaxf(lo + c3v, 0.f) * w4v;
            p3 += fmaxf(hi + c3v, 0.f) * w4v;
        }
        H3s[(4 * pg + 0) * 9 + og] = p0;
        H3s[(4 * pg + 1) * 9 + og] = p1;
        H3s[(4 * pg + 2) * 9 + og] = p2;
        H3s[(4 * pg + 3) * 9 + og] = p3;
    }
    __syncthreads();

    if (t < 128) {
        float l = b4s[0];
        #pragma unroll
        for (int q = 0; q < 8; q++) l += H3s[t * 9 + q];
        int ii = t >> 4, jj = t & 15;
        g_L[(b * NN + i0 + ii) * NN + (j0 + jj)] = l;
    }
}

// ---------------- epilogue: symmetrize + sim + sigmoid + masks ----------------
__global__ void k_epi(const int* __restrict__ masks, float* __restrict__ out,
                      int write_logits) {
    __shared__ float LT [32][33];
    __shared__ float nfI[32][65];
    __shared__ float nfJ[32][65];
    int b  = blockIdx.z;
    int i0 = blockIdx.y * 32;
    int j0 = blockIdx.x * 32;
    int tx = threadIdx.x, ty = threadIdx.y;

    LT[ty][tx] = g_L[(b * NN + j0 + ty) * NN + (i0 + tx)];
    nfI[ty][tx]      = g_nfn[(b * NN + i0 + ty) * DD + tx];
    nfI[ty][tx + 32] = g_nfn[(b * NN + i0 + ty) * DD + tx + 32];
    nfJ[ty][tx]      = g_nfn[(b * NN + j0 + ty) * DD + tx];
    nfJ[ty][tx + 32] = g_nfn[(b * NN + j0 + ty) * DD + tx + 32];
    __syncthreads();

    int i = i0 + ty, j = j0 + tx;
    float lij = g_L[(b * NN + i) * NN + j];
    float lji = LT[tx][ty];
    float lsym = (i == j) ? -10.f : 0.5f * (lij + lji);

    float sim = 0.f;
    #pragma unroll
    for (int d = 0; d < DD; d++) sim += nfI[ty][d] * nfJ[tx][d];

    float logit = (lsym + 2.f * sim) * 2.f;
    float p = 1.f / (1.f + expf(-logit));
    p = (p > 0.6f) ? p * 1.2f : p * 0.8f;
    p = fminf(fmaxf(p, 0.f), 1.f);

    bool m = (masks[b * NN + i] != 0) && (masks[b * NN + j] != 0) && (g_active[b] != 0);
    int idx = (b * NN + i) * NN + j;
    out[idx] = m ? p : 0.f;
    if (write_logits) out[BB * NN * NN + idx] = m ? logit : 0.f;
}

// ---------------- launch ----------------
extern "C" void kernel_launch(void* const* d_in, const int* in_sizes, int n_in,
                              void* d_out, int out_size) {
    const float* nf    = (const float*)d_in[0];
    const int*   masks = (const int*)  d_in[1];
    const float *W1, *b1, *W2, *b2, *W3, *b3, *W4, *b4;
    const float *g1, *be1, *m1, *v1, *g2, *be2, *m2, *v2, *g3, *be3, *m3, *v3;

    if (n_in >= 22 && in_sizes[4] == 8192) {
        W1 = (const float*)d_in[2];  b1 = (const float*)d_in[3];
        W2 = (const float*)d_in[4];  b2 = (const float*)d_in[5];
        W3 = (const float*)d_in[6];  b3 = (const float*)d_in[7];
        W4 = (const float*)d_in[8];  b4 = (const float*)d_in[9];
        g1 = (const float*)d_in[10]; be1 = (const float*)d_in[11];
        m1 = (const float*)d_in[12]; v1  = (const float*)d_in[13];
        g2 = (const float*)d_in[14]; be2 = (const float*)d_in[15];
        m2 = (const float*)d_in[16]; v2  = (const float*)d_in[17];
        g3 = (const float*)d_in[18]; be3 = (const float*)d_in[19];
        m3 = (const float*)d_in[20]; v3  = (const float*)d_in[21];
    } else {
        W1 = (const float*)d_in[2];  b1 = (const float*)d_in[3];
        g1 = (const float*)d_in[4];  be1 = (const float*)d_in[5];
        m1 = (const float*)d_in[6];  v1  = (const float*)d_in[7];
        W2 = (const float*)d_in[8];  b2 = (const float*)d_in[9];
        g2 = (const float*)d_in[10]; be2 = (const float*)d_in[11];
        m2 = (const float*)d_in[12]; v2  = (const float*)d_in[13];
        W3 = (const float*)d_in[14]; b3 = (const float*)d_in[15];
        g3 = (const float*)d_in[16]; be3 = (const float*)d_in[17];
        m3 = (const float*)d_in[18]; v3  = (const float*)d_in[19];
        W4 = (const float*)d_in[20]; b4 = (const float*)d_in[21];
    }

    static bool attr_set = false;
    if (!attr_set) {
        cudaFuncSetAttribute(k_main, cudaFuncAttributeMaxDynamicSharedMemorySize, SMEM_TOTAL);
        attr_set = true;
    }

    k_fold<<<1, 256>>>(W2, b2, g2, be2, m2, v2,
                       W3, b3, g3, be3, m3, v3, W4, b4, masks);
    k_nodes<<<BB * NN, 128>>>(nf, W1, b1, g1, be1, m1, v1);
    k_main<<<dim3(NN / 16, NN / 8, BB), 256, SMEM_TOTAL>>>();
    int wl = (out_size >= 2 * BB * NN * NN) ? 1 : 0;
    k_epi<<<dim3(NN / 32, NN / 32, BB), dim3(32, 32)>>>(masks, (float*)d_out, wl);
}

// round 5
// speedup vs baseline: 2.0356x; 2.0356x over previous
#include <cuda_runtime.h>
#include <cstdint>
#include <math.h>

#define EPS   1e-5f
#define BB    2
#define NN    512
#define DD    64

typedef unsigned long long ull;
typedef unsigned int u32;

// ---------------- device scratch ----------------
__device__ __align__(16) float g_U   [BB*NN*128];   // s1*(W1a@f), [node][128]
__device__ __align__(16) float g_V   [BB*NN*128];   // s1*(W1b@f)+bias, [node][128]
__device__ __align__(16) float g_nfn [BB*NN*DD];
__device__ __align__(16) uint4 g_W2f [16*8*32];     // B-frag packed: {bh0,bh1,bl0,bl1}
__device__ __align__(16) uint4 g_W3f [8*4*32];
__device__ float g_c2[64], g_c3[32], g_w4[32], g_b4s;
__device__ __align__(16) float g_L   [BB*NN*NN];
__device__ int   g_active[BB];

// ---------------- helpers ----------------
__device__ __forceinline__ u32 cvt_tf32(float a) {
    u32 r; asm("cvt.rna.tf32.f32 %0, %1;" : "=r"(r) : "f"(a)); return r;
}
__device__ __forceinline__ void mma8(float c[4], u32 a0, u32 a1, u32 a2, u32 a3,
                                     u32 b0, u32 b1) {
    asm("mma.sync.aligned.m16n8k8.row.col.f32.tf32.tf32.f32 "
        "{%0,%1,%2,%3}, {%4,%5,%6,%7}, {%8,%9}, {%0,%1,%2,%3};"
        : "+f"(c[0]), "+f"(c[1]), "+f"(c[2]), "+f"(c[3])
        : "r"(a0), "r"(a1), "r"(a2), "r"(a3), "r"(b0), "r"(b1));
}

// ---------------- smem layout (bytes) ----------------
#define OFF_W2F  0          /* 65536 */
#define OFF_W3F  65536      /* 16384 */
#define OFF_US   81920      /* 8*128*4   = 4096 */
#define OFF_VS   86016      /* 16*132*4  = 8448 */
#define OFF_C2   94464
#define OFF_C3   94720
#define OFF_W4   94848
#define OFF_B4   94976
#define SMEM_MM  94992

// ---------------- prep: fold BN, pack mma B-fragments, consts, active ------
__global__ void k_fold(const float* __restrict__ W2, const float* __restrict__ b2,
                       const float* __restrict__ g2, const float* __restrict__ be2,
                       const float* __restrict__ m2, const float* __restrict__ v2,
                       const float* __restrict__ W3, const float* __restrict__ b3,
                       const float* __restrict__ g3, const float* __restrict__ be3,
                       const float* __restrict__ m3, const float* __restrict__ v3,
                       const float* __restrict__ W4, const float* __restrict__ b4,
                       const int* __restrict__ masks) {
    int t = threadIdx.x;
    // W2 B-frags: idx = (ks*8 + nt)*32 + lane; b0=(k=8ks+l%4, n=8nt+l/4), b1=k+4
    for (int idx = t; idx < 16 * 8 * 32; idx += blockDim.x) {
        int ks = idx >> 8, nt = (idx >> 5) & 7, l = idx & 31;
        int k0 = 8 * ks + (l & 3), n = 8 * nt + (l >> 2);
        float s = g2[n] * rsqrtf(v2[n] + EPS);
        float w0 = W2[n * 128 + k0] * s;
        float w4v = W2[n * 128 + k0 + 4] * s;
        u32 h0 = cvt_tf32(w0), h1 = cvt_tf32(w4v);
        u32 l0 = cvt_tf32(w0 - __uint_as_float(h0));
        u32 l1 = cvt_tf32(w4v - __uint_as_float(h1));
        g_W2f[idx] = make_uint4(h0, h1, l0, l1);
    }
    // W3 B-frags
    for (int idx = t; idx < 8 * 4 * 32; idx += blockDim.x) {
        int ks = idx >> 7, nt = (idx >> 5) & 3, l = idx & 31;
        int k0 = 8 * ks + (l & 3), n = 8 * nt + (l >> 2);
        float s = g3[n] * rsqrtf(v3[n] + EPS);
        float w0 = W3[n * 64 + k0] * s;
        float w4v = W3[n * 64 + k0 + 4] * s;
        u32 h0 = cvt_tf32(w0), h1 = cvt_tf32(w4v);
        u32 l0 = cvt_tf32(w0 - __uint_as_float(h0));
        u32 l1 = cvt_tf32(w4v - __uint_as_float(h1));
        g_W3f[idx] = make_uint4(h0, h1, l0, l1);
    }
    if (t < 64) {
        float s = g2[t] * rsqrtf(v2[t] + EPS);
        g_c2[t] = (b2[t] - m2[t]) * s + be2[t];
    }
    if (t < 32) {
        float s = g3[t] * rsqrtf(v3[t] + EPS);
        g_c3[t] = (b3[t] - m3[t]) * s + be3[t];
        g_w4[t] = W4[t];
    }
    if (t == 0) g_b4s = b4[0];
    __shared__ int cnt[BB];
    if (t < BB) cnt[t] = 0;
    __syncthreads();
    for (int idx = t; idx < BB * NN; idx += blockDim.x)
        if (masks[idx] != 0) atomicAdd(&cnt[idx / NN], 1);
    __syncthreads();
    if (t < BB) g_active[t] = (cnt[t] > 1) ? 1 : 0;
}

// ---------------- prep: per-node U, V, normalized features ----------------
__global__ void k_nodes(const float* __restrict__ f,
                        const float* __restrict__ W1, const float* __restrict__ b1,
                        const float* __restrict__ g1, const float* __restrict__ be1,
                        const float* __restrict__ m1, const float* __restrict__ v1) {
    __shared__ float fs[DD];
    __shared__ float sinv;
    int node = blockIdx.x;
    int t = threadIdx.x;
    if (t < DD) fs[t] = f[node * DD + t];
    __syncthreads();
    if (t == 0) {
        float ss = 0.f;
        for (int d = 0; d < DD; d++) ss += fs[d] * fs[d];
        sinv = 1.f / fmaxf(sqrtf(ss), 1e-12f);
    }
    __syncthreads();
    if (t < DD) g_nfn[node * DD + t] = fs[t] * sinv;

    float s1 = g1[t] * rsqrtf(v1[t] + EPS);
    float u = 0.f, vv = 0.f;
    const float* wr = &W1[t * 128];
    #pragma unroll 8
    for (int d = 0; d < DD; d++) {
        u  += wr[d]      * fs[d];
        vv += wr[DD + d] * fs[d];
    }
    g_U[node * 128 + t] = u * s1;
    g_V[node * 128 + t] = vv * s1 + (b1[t] - m1[t]) * s1 + be1[t];
}

// ---------------- main: fused MLP via mma.sync tf32 (2-term split) ---------
// Persistent blocks; tile = 8 i x 16 j; warp w = i-row (i0+w) x 16 j-cols.
__global__ __launch_bounds__(256, 2)
void k_main_mma() {
    extern __shared__ __align__(16) char sm[];
    uint4* W2s = (uint4*)(sm + OFF_W2F);
    uint4* W3s = (uint4*)(sm + OFF_W3F);
    float* Us  = (float*)(sm + OFF_US);    // [w][128]
    float* Vs  = (float*)(sm + OFF_VS);    // [jj][132]
    float* c2s = (float*)(sm + OFF_C2);
    float* c3s = (float*)(sm + OFF_C3);
    float* w4s = (float*)(sm + OFF_W4);
    float* b4s = (float*)(sm + OFF_B4);

    int t = threadIdx.x;
    int w = t >> 5, l = t & 31;
    int tg = l & 3, gid = l >> 2;

    // load weight frags + consts once per block
    {
        const uint4* s4 = (const uint4*)g_W2f;
        for (int i = t; i < 16 * 8 * 32; i += 256) W2s[i] = s4[i];
        const uint4* s3 = (const uint4*)g_W3f;
        for (int i = t; i < 8 * 4 * 32; i += 256) W3s[i] = s3[i];
        if (t < 64) c2s[t] = g_c2[t];
        if (t < 32) { c3s[t] = g_c3[t]; w4s[t] = g_w4[t]; }
        if (t == 0) b4s[0] = g_b4s;
    }
    __syncthreads();

    const int NT = BB * (NN / 8) * (NN / 16);   // 4096 tiles
    for (int tile = blockIdx.x; tile < NT; tile += gridDim.x) {
        int b   = tile >> 11;
        int rem = tile & 2047;
        int i0  = (rem >> 5) << 3;
        int j0  = (rem & 31) << 4;

        // stage U (8x128) and V (16x128, pad 132)
        {
            const float4* u4 = (const float4*)&g_U[((size_t)b * NN + i0) * 128];
            ((float4*)Us)[t] = u4[t];
            #pragma unroll
            for (int q = 0; q < 2; q++) {
                int idx = t + q * 256;
                int jj = idx >> 5, kq = idx & 31;
                float4 v = ((const float4*)&g_V[((size_t)b * NN + j0 + jj) * 128])[kq];
                *(float4*)&Vs[jj * 132 + kq * 4] = v;
            }
        }
        __syncthreads();

        // ---- Layer 2: C[8 nt][4], K=128 over 16 ksteps, 3-pass tf32 split ----
        float cA[8][4];
        #pragma unroll
        for (int nt = 0; nt < 8; nt++)
            #pragma unroll
            for (int q = 0; q < 4; q++) cA[nt][q] = 0.f;

        const float* urow = &Us[w * 128];
        #pragma unroll 4
        for (int ks = 0; ks < 16; ks++) {
            int k0 = 8 * ks + tg;
            float u0 = urow[k0], u4v = urow[k0 + 4];
            float v00 = Vs[gid * 132 + k0];
            float v10 = Vs[(gid + 8) * 132 + k0];
            float v04 = Vs[gid * 132 + k0 + 4];
            float v14 = Vs[(gid + 8) * 132 + k0 + 4];
            float a0 = fmaxf(u0 + v00, 0.f);
            float a1 = fmaxf(u0 + v10, 0.f);
            float a2 = fmaxf(u4v + v04, 0.f);
            float a3 = fmaxf(u4v + v14, 0.f);
            u32 h0 = cvt_tf32(a0), h1 = cvt_tf32(a1), h2 = cvt_tf32(a2), h3 = cvt_tf32(a3);
            u32 e0 = cvt_tf32(a0 - __uint_as_float(h0));
            u32 e1 = cvt_tf32(a1 - __uint_as_float(h1));
            u32 e2 = cvt_tf32(a2 - __uint_as_float(h2));
            u32 e3 = cvt_tf32(a3 - __uint_as_float(h3));
            #pragma unroll
            for (int nt = 0; nt < 8; nt++) {
                uint4 B = W2s[(ks * 8 + nt) * 32 + l];
                mma8(cA[nt], h0, h1, h2, h3, B.x, B.y);
                mma8(cA[nt], e0, e1, e2, e3, B.x, B.y);
                mma8(cA[nt], h0, h1, h2, h3, B.z, B.w);
            }
        }

        // ---- Layer 3: A-frags from C via shuffles; C2[4 nt][4] ----
        float cB[4][4];
        #pragma unroll
        for (int nt = 0; nt < 4; nt++)
            #pragma unroll
            for (int q = 0; q < 4; q++) cB[nt][q] = 0.f;

        int s1 = (l & ~3) | (tg >> 1);
        int s2 = s1 + 2;
        #pragma unroll
        for (int ks = 0; ks < 8; ks++) {
            float cb0 = c2s[8 * ks + 2 * tg];
            float cb1 = c2s[8 * ks + 2 * tg + 1];
            float h0 = fmaxf(cA[ks][0] + cb0, 0.f);
            float h1 = fmaxf(cA[ks][1] + cb1, 0.f);
            float h2v = fmaxf(cA[ks][2] + cb0, 0.f);
            float h3v = fmaxf(cA[ks][3] + cb1, 0.f);
            u32 H0 = cvt_tf32(h0), H1 = cvt_tf32(h1), H2 = cvt_tf32(h2v), H3 = cvt_tf32(h3v);
            u32 L0 = cvt_tf32(h0  - __uint_as_float(H0));
            u32 L1 = cvt_tf32(h1  - __uint_as_float(H1));
            u32 L2 = cvt_tf32(h2v - __uint_as_float(H2));
            u32 L3 = cvt_tf32(h3v - __uint_as_float(H3));
            bool odd = (tg & 1);
            u32 x0, x1;
            // hi plane
            x0 = __shfl_sync(0xffffffffu, H0, s1); x1 = __shfl_sync(0xffffffffu, H1, s1);
            u32 a0h = odd ? x1 : x0;
            x0 = __shfl_sync(0xffffffffu, H2, s1); x1 = __shfl_sync(0xffffffffu, H3, s1);
            u32 a1h = odd ? x1 : x0;
            x0 = __shfl_sync(0xffffffffu, H0, s2); x1 = __shfl_sync(0xffffffffu, H1, s2);
            u32 a2h = odd ? x1 : x0;
            x0 = __shfl_sync(0xffffffffu, H2, s2); x1 = __shfl_sync(0xffffffffu, H3, s2);
            u32 a3h = odd ? x1 : x0;
            // lo plane
            x0 = __shfl_sync(0xffffffffu, L0, s1); x1 = __shfl_sync(0xffffffffu, L1, s1);
            u32 a0l = odd ? x1 : x0;
            x0 = __shfl_sync(0xffffffffu, L2, s1); x1 = __shfl_sync(0xffffffffu, L3, s1);
            u32 a1l = odd ? x1 : x0;
            x0 = __shfl_sync(0xffffffffu, L0, s2); x1 = __shfl_sync(0xffffffffu, L1, s2);
            u32 a2l = odd ? x1 : x0;
            x0 = __shfl_sync(0xffffffffu, L2, s2); x1 = __shfl_sync(0xffffffffu, L3, s2);
            u32 a3l = odd ? x1 : x0;
            #pragma unroll
            for (int nt = 0; nt < 4; nt++) {
                uint4 B = W3s[(ks * 4 + nt) * 32 + l];
                mma8(cB[nt], a0h, a1h, a2h, a3h, B.x, B.y);
                mma8(cB[nt], a0l, a1l, a2l, a3l, B.x, B.y);
                mma8(cB[nt], a0h, a1h, a2h, a3h, B.z, B.w);
            }
        }

        // ---- head: relu(+c3) dot w4, reduce across 4-lane group ----
        {
            float pl = 0.f, ph = 0.f;
            #pragma unroll
            for (int nt = 0; nt < 4; nt++) {
                int c0 = 8 * nt + 2 * tg, c1 = c0 + 1;
                float w0 = w4s[c0], w1 = w4s[c1];
                float b0 = c3s[c0], b1 = c3s[c1];
                pl += fmaxf(cB[nt][0] + b0, 0.f) * w0 + fmaxf(cB[nt][1] + b1, 0.f) * w1;
                ph += fmaxf(cB[nt][2] + b0, 0.f) * w0 + fmaxf(cB[nt][3] + b1, 0.f) * w1;
            }
            pl += __shfl_xor_sync(0xffffffffu, pl, 1);
            pl += __shfl_xor_sync(0xffffffffu, pl, 2);
            ph += __shfl_xor_sync(0xffffffffu, ph, 1);
            ph += __shfl_xor_sync(0xffffffffu, ph, 2);
            if (tg == 0) {
                float base = b4s[0];
                size_t row = ((size_t)b * NN + i0 + w) * NN + j0;
                g_L[row + gid]     = base + pl;
                g_L[row + gid + 8] = base + ph;
            }
        }
        __syncthreads();
    }
}

// ---------------- epilogue: symmetrize + sim + sigmoid + masks --------------
__global__ void k_epi(const int* __restrict__ masks, float* __restrict__ out,
                      int write_logits) {
    __shared__ float LT [32][33];
    __shared__ float nfI[32][65];
    __shared__ float nfJ[32][65];
    int b  = blockIdx.z;
    int i0 = blockIdx.y * 32;
    int j0 = blockIdx.x * 32;
    int tx = threadIdx.x, ty = threadIdx.y;

    LT[ty][tx] = g_L[((size_t)b * NN + j0 + ty) * NN + (i0 + tx)];
    nfI[ty][tx]      = g_nfn[((size_t)b * NN + i0 + ty) * DD + tx];
    nfI[ty][tx + 32] = g_nfn[((size_t)b * NN + i0 + ty) * DD + tx + 32];
    nfJ[ty][tx]      = g_nfn[((size_t)b * NN + j0 + ty) * DD + tx];
    nfJ[ty][tx + 32] = g_nfn[((size_t)b * NN + j0 + ty) * DD + tx + 32];
    __syncthreads();

    int i = i0 + ty, j = j0 + tx;
    float lij = g_L[((size_t)b * NN + i) * NN + j];
    float lji = LT[tx][ty];
    float lsym = (i == j) ? -10.f : 0.5f * (lij + lji);

    float sim = 0.f;
    #pragma unroll
    for (int d = 0; d < DD; d++) sim += nfI[ty][d] * nfJ[tx][d];

    float logit = (lsym + 2.f * sim) * 2.f;
    float p = 1.f / (1.f + expf(-logit));
    p = (p > 0.6f) ? p * 1.2f : p * 0.8f;
    p = fminf(fmaxf(p, 0.f), 1.f);

    bool m = (masks[b * NN + i] != 0) && (masks[b * NN + j] != 0) && (g_active[b] != 0);
    size_t idx = ((size_t)b * NN + i) * NN + j;
    out[idx] = m ? p : 0.f;
    if (write_logits) out[(size_t)BB * NN * NN + idx] = m ? logit : 0.f;
}

// ---------------- launch ----------------
extern "C" void kernel_launch(void* const* d_in, const int* in_sizes, int n_in,
                              void* d_out, int out_size) {
    const float* nf    = (const float*)d_in[0];
    const int*   masks = (const int*)  d_in[1];
    const float *W1, *b1, *W2, *b2, *W3, *b3, *W4, *b4;
    const float *g1, *be1, *m1, *v1, *g2, *be2, *m2, *v2, *g3, *be3, *m3, *v3;

    if (n_in >= 22 && in_sizes[4] == 8192) {
        W1 = (const float*)d_in[2];  b1 = (const float*)d_in[3];
        W2 = (const float*)d_in[4];  b2 = (const float*)d_in[5];
        W3 = (const float*)d_in[6];  b3 = (const float*)d_in[7];
        W4 = (const float*)d_in[8];  b4 = (const float*)d_in[9];
        g1 = (const float*)d_in[10]; be1 = (const float*)d_in[11];
        m1 = (const float*)d_in[12]; v1  = (const float*)d_in[13];
        g2 = (const float*)d_in[14]; be2 = (const float*)d_in[15];
        m2 = (const float*)d_in[16]; v2  = (const float*)d_in[17];
        g3 = (const float*)d_in[18]; be3 = (const float*)d_in[19];
        m3 = (const float*)d_in[20]; v3  = (const float*)d_in[21];
    } else {
        W1 = (const float*)d_in[2];  b1 = (const float*)d_in[3];
        g1 = (const float*)d_in[4];  be1 = (const float*)d_in[5];
        m1 = (const float*)d_in[6];  v1  = (const float*)d_in[7];
        W2 = (const float*)d_in[8];  b2 = (const float*)d_in[9];
        g2 = (const float*)d_in[10]; be2 = (const float*)d_in[11];
        m2 = (const float*)d_in[12]; v2  = (const float*)d_in[13];
        W3 = (const float*)d_in[14]; b3 = (const float*)d_in[15];
        g3 = (const float*)d_in[16]; be3 = (const float*)d_in[17];
        m3 = (const float*)d_in[18]; v3  = (const float*)d_in[19];
        W4 = (const float*)d_in[20]; b4 = (const float*)d_in[21];
    }

    static bool attr_set = false;
    if (!attr_set) {
        cudaFuncSetAttribute(k_main_mma, cudaFuncAttributeMaxDynamicSharedMemorySize, SMEM_MM);
        attr_set = true;
    }

    k_fold<<<1, 256>>>(W2, b2, g2, be2, m2, v2,
                       W3, b3, g3, be3, m3, v3, W4, b4, masks);
    k_nodes<<<BB * NN, 128>>>(nf, W1, b1, g1, be1, m1, v1);
    k_main_mma<<<296, 256, SMEM_MM>>>();
    int wl = (out_size >= 2 * BB * NN * NN) ? 1 : 0;
    k_epi<<<dim3(NN / 32, NN / 32, BB), dim3(32, 32)>>>(masks, (float*)d_out, wl);
}

// round 6
// speedup vs baseline: 2.9662x; 1.4571x over previous
#include <cuda_runtime.h>
#include <cuda_bf16.h>
#include <cstdint>
#include <math.h>

#define EPS   1e-5f
#define BB    2
#define NN    512
#define DD    64

typedef unsigned long long ull;
typedef unsigned int u32;

// ---------------- device scratch ----------------
__device__ __align__(16) float g_U   [BB*NN*128];   // s1*(W1a@f), [node][128]
__device__ __align__(16) float g_V   [BB*NN*128];   // s1*(W1b@f)+bias, [node][128]
__device__ __align__(16) float g_nfn [BB*NN*DD];
__device__ __align__(16) uint4 g_W2f [8*8*32];      // B-frag bf16: {bh0,bh1,bl0,bl1}
__device__ __align__(16) uint4 g_W3f [4*4*32];
__device__ float g_c2[64], g_c3[32], g_w4[32], g_b4s;
__device__ __align__(16) float g_L   [BB*NN*NN];
__device__ int   g_active[BB];

// ---------------- helpers ----------------
// pack two f32 -> bf16x2; e0 goes to LOW half (lower k index)
__device__ __forceinline__ u32 pk(float e0, float e1) {
    u32 r; asm("cvt.rn.bf16x2.f32 %0, %1, %2;" : "=r"(r) : "f"(e1), "f"(e0)); return r;
}
// residual pack: given pair (e0,e1) and their hi bf16x2 pack, build lo pack
__device__ __forceinline__ u32 pk_res(float e0, float e1, u32 h) {
    float r0 = __uint_as_float(h << 16);
    float r1 = __uint_as_float(h & 0xffff0000u);
    return pk(e0 - r0, e1 - r1);
}
__device__ __forceinline__ void mma16(float c[4], u32 a0, u32 a1, u32 a2, u32 a3,
                                      u32 b0, u32 b1) {
    asm("mma.sync.aligned.m16n8k16.row.col.f32.bf16.bf16.f32 "
        "{%0,%1,%2,%3}, {%4,%5,%6,%7}, {%8,%9}, {%0,%1,%2,%3};"
        : "+f"(c[0]), "+f"(c[1]), "+f"(c[2]), "+f"(c[3])
        : "r"(a0), "r"(a1), "r"(a2), "r"(a3), "r"(b0), "r"(b1));
}

// ---------------- smem layout (bytes) ----------------
#define OFF_W2F  0          /* 32768 */
#define OFF_W3F  32768      /* 8192 */
#define OFF_US   40960      /* 8*128*4  = 4096 */
#define OFF_VS   45056      /* 16*132*4 = 8448 */
#define OFF_C2   53504      /* 256 */
#define OFF_C3   53760      /* 128 */
#define OFF_W4   53888      /* 128 */
#define OFF_B4   54016
#define SMEM_MM  54032

// ---------------- prep: fold BN, pack bf16 B-fragments, consts, active -----
__global__ void k_fold(const float* __restrict__ W2, const float* __restrict__ b2,
                       const float* __restrict__ g2, const float* __restrict__ be2,
                       const float* __restrict__ m2, const float* __restrict__ v2,
                       const float* __restrict__ W3, const float* __restrict__ b3,
                       const float* __restrict__ g3, const float* __restrict__ be3,
                       const float* __restrict__ m3, const float* __restrict__ v3,
                       const float* __restrict__ W4, const float* __restrict__ b4,
                       const int* __restrict__ masks) {
    int t = threadIdx.x;
    // W2 B-frags: idx = (ks*8 + nt)*32 + l; n=8nt+(l>>2), k0=16ks+2(l&3)
    for (int idx = t; idx < 8 * 8 * 32; idx += blockDim.x) {
        int ks = idx >> 8, nt = (idx >> 5) & 7, l = idx & 31;
        int n = 8 * nt + (l >> 2), k0 = 16 * ks + 2 * (l & 3);
        float s = g2[n] * rsqrtf(v2[n] + EPS);
        float w00 = W2[n * 128 + k0] * s,     w01 = W2[n * 128 + k0 + 1] * s;
        float w10 = W2[n * 128 + k0 + 8] * s, w11 = W2[n * 128 + k0 + 9] * s;
        u32 bh0 = pk(w00, w01), bh1 = pk(w10, w11);
        g_W2f[idx] = make_uint4(bh0, bh1, pk_res(w00, w01, bh0), pk_res(w10, w11, bh1));
    }
    // W3 B-frags: idx = (ks*4 + nt)*32 + l; n=8nt+(l>>2), k0=16ks+2(l&3)
    for (int idx = t; idx < 4 * 4 * 32; idx += blockDim.x) {
        int ks = idx >> 7, nt = (idx >> 5) & 3, l = idx & 31;
        int n = 8 * nt + (l >> 2), k0 = 16 * ks + 2 * (l & 3);
        float s = g3[n] * rsqrtf(v3[n] + EPS);
        float w00 = W3[n * 64 + k0] * s,     w01 = W3[n * 64 + k0 + 1] * s;
        float w10 = W3[n * 64 + k0 + 8] * s, w11 = W3[n * 64 + k0 + 9] * s;
        u32 bh0 = pk(w00, w01), bh1 = pk(w10, w11);
        g_W3f[idx] = make_uint4(bh0, bh1, pk_res(w00, w01, bh0), pk_res(w10, w11, bh1));
    }
    if (t < 64) {
        float s = g2[t] * rsqrtf(v2[t] + EPS);
        g_c2[t] = (b2[t] - m2[t]) * s + be2[t];
    }
    if (t < 32) {
        float s = g3[t] * rsqrtf(v3[t] + EPS);
        g_c3[t] = (b3[t] - m3[t]) * s + be3[t];
        g_w4[t] = W4[t];
    }
    if (t == 0) g_b4s = b4[0];
    __shared__ int cnt[BB];
    if (t < BB) cnt[t] = 0;
    __syncthreads();
    for (int idx = t; idx < BB * NN; idx += blockDim.x)
        if (masks[idx] != 0) atomicAdd(&cnt[idx / NN], 1);
    __syncthreads();
    if (t < BB) g_active[t] = (cnt[t] > 1) ? 1 : 0;
}

// ---------------- prep: per-node U, V, normalized features ----------------
__global__ void k_nodes(const float* __restrict__ f,
                        const float* __restrict__ W1, const float* __restrict__ b1,
                        const float* __restrict__ g1, const float* __restrict__ be1,
                        const float* __restrict__ m1, const float* __restrict__ v1) {
    __shared__ float fs[DD];
    __shared__ float sinv;
    int node = blockIdx.x;
    int t = threadIdx.x;
    if (t < DD) fs[t] = f[node * DD + t];
    __syncthreads();
    if (t == 0) {
        float ss = 0.f;
        for (int d = 0; d < DD; d++) ss += fs[d] * fs[d];
        sinv = 1.f / fmaxf(sqrtf(ss), 1e-12f);
    }
    __syncthreads();
    if (t < DD) g_nfn[node * DD + t] = fs[t] * sinv;

    float s1 = g1[t] * rsqrtf(v1[t] + EPS);
    float u = 0.f, vv = 0.f;
    const float* wr = &W1[t * 128];
    #pragma unroll 8
    for (int d = 0; d < DD; d++) {
        u  += wr[d]      * fs[d];
        vv += wr[DD + d] * fs[d];
    }
    g_U[node * 128 + t] = u * s1;
    g_V[node * 128 + t] = vv * s1 + (b1[t] - m1[t]) * s1 + be1[t];
}

// ---------------- main: fused MLP via mma.sync bf16 k16 (2-term split) -----
// Persistent blocks; tile = 8 i x 16 j; warp w = i-row (i0+w) x 16 j-cols.
__global__ __launch_bounds__(256, 2)
void k_main_mma() {
    extern __shared__ __align__(16) char sm[];
    uint4* W2s = (uint4*)(sm + OFF_W2F);
    uint4* W3s = (uint4*)(sm + OFF_W3F);
    float* Us  = (float*)(sm + OFF_US);    // [w][128]
    float* Vs  = (float*)(sm + OFF_VS);    // [jj][132]
    float* c2s = (float*)(sm + OFF_C2);
    float* c3s = (float*)(sm + OFF_C3);
    float* w4s = (float*)(sm + OFF_W4);
    float* b4s = (float*)(sm + OFF_B4);

    int t = threadIdx.x;
    int w = t >> 5, l = t & 31;
    int tg = l & 3, gid = l >> 2;

    {
        const uint4* s4 = (const uint4*)g_W2f;
        for (int i = t; i < 8 * 8 * 32; i += 256) W2s[i] = s4[i];
        const uint4* s3 = (const uint4*)g_W3f;
        for (int i = t; i < 4 * 4 * 32; i += 256) W3s[i] = s3[i];
        if (t < 64) c2s[t] = g_c2[t];
        if (t < 32) { c3s[t] = g_c3[t]; w4s[t] = g_w4[t]; }
        if (t == 0) b4s[0] = g_b4s;
    }
    __syncthreads();

    const int NT = BB * (NN / 8) * (NN / 16);   // 4096 tiles
    for (int tile = blockIdx.x; tile < NT; tile += gridDim.x) {
        int b   = tile >> 11;
        int rem = tile & 2047;
        int i0  = (rem >> 5) << 3;
        int j0  = (rem & 31) << 4;

        // stage U (8x128) and V (16x128, pad 132)
        {
            const float4* u4 = (const float4*)&g_U[((size_t)b * NN + i0) * 128];
            ((float4*)Us)[t] = u4[t];
            #pragma unroll
            for (int q = 0; q < 2; q++) {
                int idx = t + q * 256;
                int jj = idx >> 5, kq = idx & 31;
                float4 v = ((const float4*)&g_V[((size_t)b * NN + j0 + jj) * 128])[kq];
                *(float4*)&Vs[jj * 132 + kq * 4] = v;
            }
        }
        __syncthreads();

        // ---- Layer 2: C[8 nt][4], K=128 over 8 k16-steps, 3-pass bf16 ----
        float cA[8][4];
        #pragma unroll
        for (int nt = 0; nt < 8; nt++)
            #pragma unroll
            for (int q = 0; q < 4; q++) cA[nt][q] = 0.f;

        const float* urow = &Us[w * 128];
        #pragma unroll
        for (int ks = 0; ks < 8; ks++) {
            int k0 = 16 * ks + 2 * tg;
            float2 uA  = *(const float2*)&urow[k0];
            float2 uB  = *(const float2*)&urow[k0 + 8];
            float2 v0A = *(const float2*)&Vs[gid * 132 + k0];
            float2 v1A = *(const float2*)&Vs[(gid + 8) * 132 + k0];
            float2 v0B = *(const float2*)&Vs[gid * 132 + k0 + 8];
            float2 v1B = *(const float2*)&Vs[(gid + 8) * 132 + k0 + 8];
            float e00 = fmaxf(uA.x + v0A.x, 0.f), e01 = fmaxf(uA.y + v0A.y, 0.f);
            float e10 = fmaxf(uA.x + v1A.x, 0.f), e11 = fmaxf(uA.y + v1A.y, 0.f);
            float e20 = fmaxf(uB.x + v0B.x, 0.f), e21 = fmaxf(uB.y + v0B.y, 0.f);
            float e30 = fmaxf(uB.x + v1B.x, 0.f), e31 = fmaxf(uB.y + v1B.y, 0.f);
            u32 a0h = pk(e00, e01), a1h = pk(e10, e11);
            u32 a2h = pk(e20, e21), a3h = pk(e30, e31);
            u32 a0l = pk_res(e00, e01, a0h), a1l = pk_res(e10, e11, a1h);
            u32 a2l = pk_res(e20, e21, a2h), a3l = pk_res(e30, e31, a3h);
            #pragma unroll
            for (int nt = 0; nt < 8; nt++) {
                uint4 B = W2s[(ks * 8 + nt) * 32 + l];
                mma16(cA[nt], a0h, a1h, a2h, a3h, B.x, B.y);
                mma16(cA[nt], a0l, a1l, a2l, a3l, B.x, B.y);
                mma16(cA[nt], a0h, a1h, a2h, a3h, B.z, B.w);
            }
        }

        // ---- Layer 3: A-frags align with C-frags lane-exactly (no shuffles) ----
        float cB[4][4];
        #pragma unroll
        for (int nt = 0; nt < 4; nt++)
            #pragma unroll
            for (int q = 0; q < 4; q++) cB[nt][q] = 0.f;

        #pragma unroll
        for (int ks = 0; ks < 4; ks++) {
            int n0 = 2 * ks, n1 = n0 + 1;
            float cb00 = c2s[8 * n0 + 2 * tg], cb01 = c2s[8 * n0 + 2 * tg + 1];
            float cb10 = c2s[8 * n1 + 2 * tg], cb11 = c2s[8 * n1 + 2 * tg + 1];
            float e00 = fmaxf(cA[n0][0] + cb00, 0.f), e01 = fmaxf(cA[n0][1] + cb01, 0.f);
            float e10 = fmaxf(cA[n0][2] + cb00, 0.f), e11 = fmaxf(cA[n0][3] + cb01, 0.f);
            float e20 = fmaxf(cA[n1][0] + cb10, 0.f), e21 = fmaxf(cA[n1][1] + cb11, 0.f);
            float e30 = fmaxf(cA[n1][2] + cb10, 0.f), e31 = fmaxf(cA[n1][3] + cb11, 0.f);
            u32 a0h = pk(e00, e01), a1h = pk(e10, e11);
            u32 a2h = pk(e20, e21), a3h = pk(e30, e31);
            u32 a0l = pk_res(e00, e01, a0h), a1l = pk_res(e10, e11, a1h);
            u32 a2l = pk_res(e20, e21, a2h), a3l = pk_res(e30, e31, a3h);
            #pragma unroll
            for (int nt = 0; nt < 4; nt++) {
                uint4 B = W3s[(ks * 4 + nt) * 32 + l];
                mma16(cB[nt], a0h, a1h, a2h, a3h, B.x, B.y);
                mma16(cB[nt], a0l, a1l, a2l, a3l, B.x, B.y);
                mma16(cB[nt], a0h, a1h, a2h, a3h, B.z, B.w);
            }
        }

        // ---- head: relu(+c3) dot w4, reduce across 4-lane group ----
        {
            float pl = 0.f, ph = 0.f;
            #pragma unroll
            for (int nt = 0; nt < 4; nt++) {
                int c0 = 8 * nt + 2 * tg, c1 = c0 + 1;
                float w0 = w4s[c0], w1 = w4s[c1];
                float b0 = c3s[c0], b1 = c3s[c1];
                pl += fmaxf(cB[nt][0] + b0, 0.f) * w0 + fmaxf(cB[nt][1] + b1, 0.f) * w1;
                ph += fmaxf(cB[nt][2] + b0, 0.f) * w0 + fmaxf(cB[nt][3] + b1, 0.f) * w1;
            }
            pl += __shfl_xor_sync(0xffffffffu, pl, 1);
            pl += __shfl_xor_sync(0xffffffffu, pl, 2);
            ph += __shfl_xor_sync(0xffffffffu, ph, 1);
            ph += __shfl_xor_sync(0xffffffffu, ph, 2);
            if (tg == 0) {
                float base = b4s[0];
                size_t row = ((size_t)b * NN + i0 + w) * NN + j0;
                g_L[row + gid]     = base + pl;
                g_L[row + gid + 8] = base + ph;
            }
        }
        __syncthreads();
    }
}

// ---------------- epilogue: symmetrize + sim + sigmoid + masks --------------
__global__ void k_epi(const int* __restrict__ masks, float* __restrict__ out,
                      int write_logits) {
    __shared__ float LT [32][33];
    __shared__ float nfI[32][65];
    __shared__ float nfJ[32][65];
    int b  = blockIdx.z;
    int i0 = blockIdx.y * 32;
    int j0 = blockIdx.x * 32;
    int tx = threadIdx.x, ty = threadIdx.y;

    LT[ty][tx] = g_L[((size_t)b * NN + j0 + ty) * NN + (i0 + tx)];
    nfI[ty][tx]      = g_nfn[((size_t)b * NN + i0 + ty) * DD + tx];
    nfI[ty][tx + 32] = g_nfn[((size_t)b * NN + i0 + ty) * DD + tx + 32];
    nfJ[ty][tx]      = g_nfn[((size_t)b * NN + j0 + ty) * DD + tx];
    nfJ[ty][tx + 32] = g_nfn[((size_t)b * NN + j0 + ty) * DD + tx + 32];
    __syncthreads();

    int i = i0 + ty, j = j0 + tx;
    float lij = g_L[((size_t)b * NN + i) * NN + j];
    float lji = LT[tx][ty];
    float lsym = (i == j) ? -10.f : 0.5f * (lij + lji);

    float sim = 0.f;
    #pragma unroll
    for (int d = 0; d < DD; d++) sim += nfI[ty][d] * nfJ[tx][d];

    float logit = (lsym + 2.f * sim) * 2.f;
    float p = 1.f / (1.f + expf(-logit));
    p = (p > 0.6f) ? p * 1.2f : p * 0.8f;
    p = fminf(fmaxf(p, 0.f), 1.f);

    bool m = (masks[b * NN + i] != 0) && (masks[b * NN + j] != 0) && (g_active[b] != 0);
    size_t idx = ((size_t)b * NN + i) * NN + j;
    out[idx] = m ? p : 0.f;
    if (write_logits) out[(size_t)BB * NN * NN + idx] = m ? logit : 0.f;
}

// ---------------- launch ----------------
extern "C" void kernel_launch(void* const* d_in, const int* in_sizes, int n_in,
                              void* d_out, int out_size) {
    const float* nf    = (const float*)d_in[0];
    const int*   masks = (const int*)  d_in[1];
    const float *W1, *b1, *W2, *b2, *W3, *b3, *W4, *b4;
    const float *g1, *be1, *m1, *v1, *g2, *be2, *m2, *v2, *g3, *be3, *m3, *v3;

    if (n_in >= 22 && in_sizes[4] == 8192) {
        W1 = (const float*)d_in[2];  b1 = (const float*)d_in[3];
        W2 = (const float*)d_in[4];  b2 = (const float*)d_in[5];
        W3 = (const float*)d_in[6];  b3 = (const float*)d_in[7];
        W4 = (const float*)d_in[8];  b4 = (const float*)d_in[9];
        g1 = (const float*)d_in[10]; be1 = (const float*)d_in[11];
        m1 = (const float*)d_in[12]; v1  = (const float*)d_in[13];
        g2 = (const float*)d_in[14]; be2 = (const float*)d_in[15];
        m2 = (const float*)d_in[16]; v2  = (const float*)d_in[17];
        g3 = (const float*)d_in[18]; be3 = (const float*)d_in[19];
        m3 = (const float*)d_in[20]; v3  = (const float*)d_in[21];
    } else {
        W1 = (const float*)d_in[2];  b1 = (const float*)d_in[3];
        g1 = (const float*)d_in[4];  be1 = (const float*)d_in[5];
        m1 = (const float*)d_in[6];  v1  = (const float*)d_in[7];
        W2 = (const float*)d_in[8];  b2 = (const float*)d_in[9];
        g2 = (const float*)d_in[10]; be2 = (const float*)d_in[11];
        m2 = (const float*)d_in[12]; v2  = (const float*)d_in[13];
        W3 = (const float*)d_in[14]; b3 = (const float*)d_in[15];
        g3 = (const float*)d_in[16]; be3 = (const float*)d_in[17];
        m3 = (const float*)d_in[18]; v3  = (const float*)d_in[19];
        W4 = (const float*)d_in[20]; b4 = (const float*)d_in[21];
    }

    static bool attr_set = false;
    if (!attr_set) {
        cudaFuncSetAttribute(k_main_mma, cudaFuncAttributeMaxDynamicSharedMemorySize, SMEM_MM);
        attr_set = true;
    }

    k_fold<<<1, 256>>>(W2, b2, g2, be2, m2, v2,
                       W3, b3, g3, be3, m3, v3, W4, b4, masks);
    k_nodes<<<BB * NN, 128>>>(nf, W1, b1, g1, be1, m1, v1);
    k_main_mma<<<296, 256, SMEM_MM>>>();
    int wl = (out_size >= 2 * BB * NN * NN) ? 1 : 0;
    k_epi<<<dim3(NN / 32, NN / 32, BB), dim3(32, 32)>>>(masks, (float*)d_out, wl);
}